// round 7
// baseline (speedup 1.0000x reference)
#include <cuda_runtime.h>
#include <math.h>
#include <stdint.h>

#define NE 64
#define NH 512
#define NF 2048
#define NT 2048

// scratch: h = gelu(x @ w1^T) (16 MB)
__device__ float g_h[(size_t)NT * NF];

// ---------------- helpers ----------------
__device__ __forceinline__ uint32_t smem_u32(const void* p) {
    return (uint32_t)__cvta_generic_to_shared(p);
}
__device__ __forceinline__ uint32_t sw128(uint32_t off) { return off ^ ((off >> 3) & 0x70); }

__device__ __forceinline__ void bar_syn(int id) {
    asm volatile("bar.sync %0, 384;" :: "r"(id) : "memory");
}
__device__ __forceinline__ void bar_arr(int id) {
    asm volatile("bar.arrive %0, 384;" :: "r"(id) : "memory");
}

__device__ __forceinline__ void ldm_x4(uint32_t* r, uint32_t a) {
    asm volatile("ldmatrix.sync.aligned.m8n8.x4.shared.b16 {%0,%1,%2,%3}, [%4];"
                 : "=r"(r[0]), "=r"(r[1]), "=r"(r[2]), "=r"(r[3]) : "r"(a));
}
__device__ __forceinline__ void ldm_x4_t(uint32_t* r, uint32_t a) {
    asm volatile("ldmatrix.sync.aligned.m8n8.x4.trans.shared.b16 {%0,%1,%2,%3}, [%4];"
                 : "=r"(r[0]), "=r"(r[1]), "=r"(r[2]), "=r"(r[3]) : "r"(a));
}
__device__ __forceinline__ void mma_bf16(float* c, const uint32_t* a, const uint32_t* b) {
    asm volatile(
        "mma.sync.aligned.m16n8k16.row.col.f32.bf16.bf16.f32 "
        "{%0,%1,%2,%3}, {%4,%5,%6,%7}, {%8,%9}, {%0,%1,%2,%3};"
        : "+f"(c[0]), "+f"(c[1]), "+f"(c[2]), "+f"(c[3])
        : "r"(a[0]), "r"(a[1]), "r"(a[2]), "r"(a[3]), "r"(b[0]), "r"(b[1]));
}
__device__ __forceinline__ float gelu_exact(float v) {
    return 0.5f * v * (1.0f + erff(v * 0.7071067811865476f));
}

__device__ __forceinline__ void expert_range(const int* __restrict__ counts, int e,
                                             int& base, int& cnt) {
    int b = 0, c = 0;
    #pragma unroll
    for (int j = 0; j < NE; ++j) {
        const int v = __ldg(counts + j);
        if (j < e) b += v;
        if (j == e) c = v;
    }
    base = b; cnt = c;
}

__device__ __forceinline__ void split4(const float4 t, uint64_t& hi, uint64_t& lo) {
    uint32_t h01, h23, l01, l23;
    asm("cvt.rn.bf16x2.f32 %0, %1, %2;" : "=r"(h01) : "f"(t.y), "f"(t.x));
    asm("cvt.rn.bf16x2.f32 %0, %1, %2;" : "=r"(h23) : "f"(t.w), "f"(t.z));
    const float rx = t.x - __uint_as_float(h01 << 16);
    const float ry = t.y - __uint_as_float(h01 & 0xffff0000u);
    const float rz = t.z - __uint_as_float(h23 << 16);
    const float rw = t.w - __uint_as_float(h23 & 0xffff0000u);
    asm("cvt.rn.bf16x2.f32 %0, %1, %2;" : "=r"(l01) : "f"(ry), "f"(rx));
    asm("cvt.rn.bf16x2.f32 %0, %1, %2;" : "=r"(l23) : "f"(rw), "f"(rz));
    hi = ((uint64_t)h23 << 32) | h01;
    lo = ((uint64_t)l23 << 32) | l01;
}

// ---- producer tile ops: 64 rows x 64 f32, 128 threads (ptid 0..127) ----
__device__ __forceinline__ void ldgP(float4* v, const float* __restrict__ src,
                                     int stride, int valid, int ptid) {
    const int r0 = ptid >> 4, c4 = (ptid & 15) * 4;
    #pragma unroll
    for (int p = 0; p < 8; ++p) {
        const int row = p * 8 + r0;
        v[p] = (row < valid) ? *(const float4*)(src + (size_t)row * stride + c4)
                             : make_float4(0.f, 0.f, 0.f, 0.f);
    }
}
__device__ __forceinline__ void stsP(const float4* v, char* hi, char* lo, int ptid) {
    const int r0 = ptid >> 4, l15 = ptid & 15;
    #pragma unroll
    for (int p = 0; p < 8; ++p) {
        const int row = p * 8 + r0;
        uint64_t h, l;
        split4(v[p], h, l);
        const uint32_t off = sw128((uint32_t)(row * 128 + l15 * 8));
        *(uint64_t*)(hi + off) = h;
        *(uint64_t*)(lo + off) = l;
    }
}

// stage slot: [Ahi 8K][Alo 8K][Bhi 8K][Blo 8K] = 32K; 3 slots = 96K
#define KSLOT (32 * 1024)
#define NSLOT 3
// named barriers: full[s] = 1+s, empty[s] = 4+s

// ---------------- GEMM1 + GELU: h = gelu(x @ w1[e]^T) ------------------------
// CTA: (f-slab 64, expert). M=64 padded, K-tiles of 64 (8).
// warps 0-7 consumers (2m x 4n, warp tile 32x16); warps 8-11 producers.
__global__ void __launch_bounds__(384, 2) gemm1_tc(const float* __restrict__ x,
                                                   const float* __restrict__ w1,
                                                   const int* __restrict__ counts) {
    extern __shared__ char sm[];
    const int e  = blockIdx.y;
    const int f0 = blockIdx.x * 64;
    int base, cnt;
    expert_range(counts, e, base, cnt);
    const int tid = threadIdx.x, warp = tid >> 5, lane = tid & 31;
    const bool producer = warp >= 8;
    const int ptid = tid - 256;
    const int wm = warp >> 2, wn = warp & 3;
    const float* w1e = w1 + (size_t)e * NF * NH + (size_t)f0 * NH;

    const int arow = lane & 15, acol = lane & 16;        // A (plain)
    const int brow = (lane & 7) + ((lane >> 1) & 8);     // B (plain, [n][k])
    const int bcol = (lane & 8) * 2;

    int g = 0;
    for (int mm = 0; mm < cnt; mm += 64) {
        const int rem = cnt - mm;
        const int va = rem < 64 ? rem : 64;
        const float* xa = x + (size_t)(base + mm) * NH;

        float c[2][2][4];
        if (!producer) {
            #pragma unroll
            for (int i = 0; i < 2; ++i)
                #pragma unroll
                for (int j = 0; j < 2; ++j)
                    #pragma unroll
                    for (int q = 0; q < 4; ++q) c[i][j][q] = 0.f;
        }

        for (int kt = 0; kt < 8; ++kt, ++g) {
            const int slot = g % NSLOT;
            char* bb = sm + slot * KSLOT;
            if (producer) {
                if (g >= NSLOT) bar_syn(4 + slot);
                float4 rA[8], rB[8];
                ldgP(rA, xa + kt * 64, NH, va, ptid);
                ldgP(rB, w1e + kt * 64, NH, 64, ptid);
                stsP(rA, bb, bb + 8192, ptid);
                stsP(rB, bb + 16384, bb + 24576, ptid);
                bar_arr(1 + slot);
            } else {
                bar_syn(1 + slot);
                const uint32_t uAh = smem_u32(bb), uAl = uAh + 8192;
                const uint32_t uBh = uAh + 16384, uBl = uAh + 24576;
                #pragma unroll
                for (int kk = 0; kk < 4; ++kk) {
                    uint32_t ah[2][4], al[2][4];
                    #pragma unroll
                    for (int mi = 0; mi < 2; ++mi) {
                        const uint32_t off =
                            sw128((uint32_t)((wm * 32 + mi * 16 + arow) * 128 + kk * 32 + acol));
                        ldm_x4(ah[mi], uAh + off);
                        ldm_x4(al[mi], uAl + off);
                    }
                    uint32_t bh[4], bl[4];
                    {
                        const uint32_t off =
                            sw128((uint32_t)((wn * 16 + brow) * 128 + kk * 32 + bcol));
                        ldm_x4(bh, uBh + off);
                        ldm_x4(bl, uBl + off);
                    }
                    #pragma unroll
                    for (int mi = 0; mi < 2; ++mi)
                        #pragma unroll
                        for (int j = 0; j < 2; ++j) {
                            float* cc = c[mi][j];
                            mma_bf16(cc, ah[mi], &bh[j * 2]);
                            mma_bf16(cc, ah[mi], &bl[j * 2]);
                            mma_bf16(cc, al[mi], &bh[j * 2]);
                        }
                }
                bar_arr(4 + slot);
            }
        }

        if (!producer) {
            const int r0 = lane >> 2, cp = (lane & 3) * 2;
            #pragma unroll
            for (int mi = 0; mi < 2; ++mi)
                #pragma unroll
                for (int nj = 0; nj < 2; ++nj) {
                    const int rloc = wm * 32 + mi * 16 + r0;
                    const int ncol = f0 + wn * 16 + nj * 8 + cp;
                    if (rloc < va) {
                        float2 o = make_float2(gelu_exact(c[mi][nj][0]),
                                               gelu_exact(c[mi][nj][1]));
                        *(float2*)&g_h[(size_t)(base + mm + rloc) * NF + ncol] = o;
                    }
                    if (rloc + 8 < va) {
                        float2 o = make_float2(gelu_exact(c[mi][nj][2]),
                                               gelu_exact(c[mi][nj][3]));
                        *(float2*)&g_h[(size_t)(base + mm + rloc + 8) * NF + ncol] = o;
                    }
                }
        }
    }
}

// ---------------- GEMM2: out = h @ w2[e]  (w2 [k][n] -> ldmatrix.trans) ------
// CTA: (n-slab 64, expert). M=64 padded, K-tiles of 64 (32).
__global__ void __launch_bounds__(384, 2) gemm2_tc(const float* __restrict__ w2,
                                                   float* __restrict__ out,
                                                   const int* __restrict__ counts) {
    extern __shared__ char sm[];
    const int e  = blockIdx.y;
    const int n0 = blockIdx.x * 64;
    int base, cnt;
    expert_range(counts, e, base, cnt);
    const int tid = threadIdx.x, warp = tid >> 5, lane = tid & 31;
    const bool producer = warp >= 8;
    const int ptid = tid - 256;
    const int wm = warp >> 2, wn = warp & 3;
    const float* w2e = w2 + (size_t)e * NF * NH + n0;

    const int arow = lane & 15, acol = lane & 16;   // A (plain)
    const int tbrow = lane & 15, tbcol = lane & 16; // B (trans, [k][n])

    int g = 0;
    for (int mm = 0; mm < cnt; mm += 64) {
        const int rem = cnt - mm;
        const int va = rem < 64 ? rem : 64;
        const float* ha = g_h + (size_t)(base + mm) * NF;

        float c[2][2][4];
        if (!producer) {
            #pragma unroll
            for (int i = 0; i < 2; ++i)
                #pragma unroll
                for (int j = 0; j < 2; ++j)
                    #pragma unroll
                    for (int q = 0; q < 4; ++q) c[i][j][q] = 0.f;
        }

        for (int kt = 0; kt < 32; ++kt, ++g) {
            const int slot = g % NSLOT;
            char* bb = sm + slot * KSLOT;
            if (producer) {
                if (g >= NSLOT) bar_syn(4 + slot);
                float4 rA[8], rB[8];
                ldgP(rA, ha + kt * 64, NF, va, ptid);
                ldgP(rB, w2e + (size_t)(kt * 64) * NH, NH, 64, ptid);
                stsP(rA, bb, bb + 8192, ptid);
                stsP(rB, bb + 16384, bb + 24576, ptid);
                bar_arr(1 + slot);
            } else {
                bar_syn(1 + slot);
                const uint32_t uAh = smem_u32(bb), uAl = uAh + 8192;
                const uint32_t uBh = uAh + 16384, uBl = uAh + 24576;
                #pragma unroll
                for (int kk = 0; kk < 4; ++kk) {
                    uint32_t ah[2][4], al[2][4];
                    #pragma unroll
                    for (int mi = 0; mi < 2; ++mi) {
                        const uint32_t off =
                            sw128((uint32_t)((wm * 32 + mi * 16 + arow) * 128 + kk * 32 + acol));
                        ldm_x4(ah[mi], uAh + off);
                        ldm_x4(al[mi], uAl + off);
                    }
                    uint32_t bh[4], bl[4];
                    {
                        const uint32_t off =
                            sw128((uint32_t)((kk * 16 + tbrow) * 128 + wn * 32 + tbcol));
                        ldm_x4_t(bh, uBh + off);
                        ldm_x4_t(bl, uBl + off);
                    }
                    #pragma unroll
                    for (int mi = 0; mi < 2; ++mi)
                        #pragma unroll
                        for (int j = 0; j < 2; ++j) {
                            float* cc = c[mi][j];
                            mma_bf16(cc, ah[mi], &bh[j * 2]);
                            mma_bf16(cc, ah[mi], &bl[j * 2]);
                            mma_bf16(cc, al[mi], &bh[j * 2]);
                        }
                }
                bar_arr(4 + slot);
            }
        }

        if (!producer) {
            const int r0 = lane >> 2, cp = (lane & 3) * 2;
            #pragma unroll
            for (int mi = 0; mi < 2; ++mi)
                #pragma unroll
                for (int nj = 0; nj < 2; ++nj) {
                    const int rloc = wm * 32 + mi * 16 + r0;
                    const int ncol = n0 + wn * 16 + nj * 8 + cp;
                    if (rloc < va)
                        *(float2*)&out[(size_t)(base + mm + rloc) * NH + ncol] =
                            make_float2(c[mi][nj][0], c[mi][nj][1]);
                    if (rloc + 8 < va)
                        *(float2*)&out[(size_t)(base + mm + rloc + 8) * NH + ncol] =
                            make_float2(c[mi][nj][2], c[mi][nj][3]);
                }
        }
    }
}

// ---------------------------------------------------------------------------
extern "C" void kernel_launch(void* const* d_in, const int* in_sizes, int n_in,
                              void* d_out, int out_size) {
    const float* x  = (const float*)d_in[0];
    const float* w1 = (const float*)d_in[1];
    const float* w2 = (const float*)d_in[2];
    const int* tokens_per_expert = (const int*)d_in[3];
    float* out = (float*)d_out;

    cudaFuncSetAttribute(gemm1_tc, cudaFuncAttributeMaxDynamicSharedMemorySize,
                         NSLOT * KSLOT);
    cudaFuncSetAttribute(gemm2_tc, cudaFuncAttributeMaxDynamicSharedMemorySize,
                         NSLOT * KSLOT);

    gemm1_tc<<<dim3(NF / 64, NE), 384, NSLOT * KSLOT>>>(x, w1, tokens_per_expert);
    gemm2_tc<<<dim3(NH / 64, NE), 384, NSLOT * KSLOT>>>(w2, out, tokens_per_expert);
}

// round 8
// speedup vs baseline: 1.2932x; 1.2932x over previous
#include <cuda_runtime.h>
#include <math.h>
#include <stdint.h>

#define NE 64
#define NH 512
#define NF 2048
#define NT 2048

// scratch: h = gelu(x @ w1^T) (16 MB)
__device__ float g_h[(size_t)NT * NF];

// ---------------- helpers ----------------
__device__ __forceinline__ uint32_t smem_u32(const void* p) {
    return (uint32_t)__cvta_generic_to_shared(p);
}
__device__ __forceinline__ uint32_t sw128(uint32_t off) { return off ^ ((off >> 3) & 0x70); }

__device__ __forceinline__ void ldm_x4(uint32_t* r, uint32_t a) {
    asm volatile("ldmatrix.sync.aligned.m8n8.x4.shared.b16 {%0,%1,%2,%3}, [%4];"
                 : "=r"(r[0]), "=r"(r[1]), "=r"(r[2]), "=r"(r[3]) : "r"(a));
}
__device__ __forceinline__ void ldm_x4_t(uint32_t* r, uint32_t a) {
    asm volatile("ldmatrix.sync.aligned.m8n8.x4.trans.shared.b16 {%0,%1,%2,%3}, [%4];"
                 : "=r"(r[0]), "=r"(r[1]), "=r"(r[2]), "=r"(r[3]) : "r"(a));
}
__device__ __forceinline__ void mma_bf16(float* c, const uint32_t* a, const uint32_t* b) {
    asm volatile(
        "mma.sync.aligned.m16n8k16.row.col.f32.bf16.bf16.f32 "
        "{%0,%1,%2,%3}, {%4,%5,%6,%7}, {%8,%9}, {%0,%1,%2,%3};"
        : "+f"(c[0]), "+f"(c[1]), "+f"(c[2]), "+f"(c[3])
        : "r"(a[0]), "r"(a[1]), "r"(a[2]), "r"(a[3]), "r"(b[0]), "r"(b[1]));
}
__device__ __forceinline__ float gelu_exact(float v) {
    return 0.5f * v * (1.0f + erff(v * 0.7071067811865476f));
}

__device__ __forceinline__ void expert_range(const int* __restrict__ counts, int e,
                                             int& base, int& cnt) {
    int b = 0, c = 0;
    #pragma unroll
    for (int j = 0; j < NE; ++j) {
        const int v = __ldg(counts + j);
        if (j < e) b += v;
        if (j == e) c = v;
    }
    base = b; cnt = c;
}

// ---------------- f32 tile load (regs) + split-convert store (smem) ----------
// Tile: 64 rows x 64 f32 cols. 256 threads: 16 threads/row (float4), 16 rows/pass.
__device__ __forceinline__ void load_f32(float4* v, const float* __restrict__ src,
                                         int stride, int valid, int tid) {
    const int row0 = tid >> 4, c4 = (tid & 15) * 4;
    #pragma unroll
    for (int p = 0; p < 4; ++p) {
        const int row = p * 16 + row0;
        v[p] = (row < valid) ? *(const float4*)(src + (size_t)row * stride + c4)
                             : make_float4(0.f, 0.f, 0.f, 0.f);
    }
}
__device__ __forceinline__ void store_split(const float4* v, char* hi, char* lo, int tid) {
    const int row0 = tid >> 4, l15 = tid & 15;
    #pragma unroll
    for (int p = 0; p < 4; ++p) {
        const int row = p * 16 + row0;
        const float4 t = v[p];
        uint32_t h01, h23, l01, l23;
        asm("cvt.rn.bf16x2.f32 %0, %1, %2;" : "=r"(h01) : "f"(t.y), "f"(t.x));
        asm("cvt.rn.bf16x2.f32 %0, %1, %2;" : "=r"(h23) : "f"(t.w), "f"(t.z));
        const float rx = t.x - __uint_as_float(h01 << 16);
        const float ry = t.y - __uint_as_float(h01 & 0xffff0000u);
        const float rz = t.z - __uint_as_float(h23 << 16);
        const float rw = t.w - __uint_as_float(h23 & 0xffff0000u);
        asm("cvt.rn.bf16x2.f32 %0, %1, %2;" : "=r"(l01) : "f"(ry), "f"(rx));
        asm("cvt.rn.bf16x2.f32 %0, %1, %2;" : "=r"(l23) : "f"(rw), "f"(rz));
        const uint32_t off = sw128((uint32_t)(row * 128 + l15 * 8));
        *(uint64_t*)(hi + off) = ((uint64_t)h23 << 32) | h01;
        *(uint64_t*)(lo + off) = ((uint64_t)l23 << 32) | l01;
    }
}

// Buffer layout per stage: [Ahi 8K][Alo 8K][Bhi 8K][Blo 8K] = 32K; x2 = 64K
#define BSZ (32 * 1024)

// ---------------- GEMM1 + GELU: h = gelu(x @ w1[e]^T) ------------------------
// CTA: (f-slab 64, expert). M=64 padded, K-tiles of 64 (8). 8 warps = 2m x 4n.
__global__ void __launch_bounds__(256, 2) gemm1_tc(const float* __restrict__ x,
                                                   const float* __restrict__ w1,
                                                   const int* __restrict__ counts) {
    extern __shared__ char sm[];
    const int e  = blockIdx.y;
    const int f0 = blockIdx.x * 64;
    int base, cnt;
    expert_range(counts, e, base, cnt);
    const int tid = threadIdx.x, warp = tid >> 5, lane = tid & 31;
    const int wm = warp >> 2, wn = warp & 3;
    const float* w1e = w1 + (size_t)e * NF * NH + (size_t)f0 * NH;

    const int arow = lane & 15, acol = lane & 16;        // A (plain)
    const int brow = (lane & 7) + ((lane >> 1) & 8);     // B (plain, [n][k])
    const int bcol = (lane & 8) * 2;

    for (int mm = 0; mm < cnt; mm += 64) {
        const int rem = cnt - mm;
        const int va = rem < 64 ? rem : 64;
        const float* xa = x + (size_t)(base + mm) * NH;

        float c[2][2][4];
        #pragma unroll
        for (int i = 0; i < 2; ++i)
            #pragma unroll
            for (int j = 0; j < 2; ++j)
                #pragma unroll
                for (int q = 0; q < 4; ++q) c[i][j][q] = 0.f;

        // prologue: stage tile 0 into buf 0
        {
            float4 rA[4], rB[4];
            load_f32(rA, xa, NH, va, tid);
            load_f32(rB, w1e, NH, 64, tid);
            store_split(rA, sm, sm + 8192, tid);
            store_split(rB, sm + 16384, sm + 24576, tid);
        }

        for (int kt = 0; kt < 8; ++kt) {
            __syncthreads();
            char* bb = sm + (kt & 1) * BSZ;
            char* nb = sm + ((kt + 1) & 1) * BSZ;
            const bool pf = (kt + 1) < 8;
            float4 rA[4], rB[4];
            if (pf) {
                const int k0 = (kt + 1) * 64;
                load_f32(rA, xa + k0, NH, va, tid);
                load_f32(rB, w1e + k0, NH, 64, tid);
            }
            const uint32_t uAh = smem_u32(bb), uAl = uAh + 8192;
            const uint32_t uBh = uAh + 16384, uBl = uAh + 24576;
            #pragma unroll
            for (int kk = 0; kk < 4; ++kk) {
                uint32_t ah[2][4], al[2][4];
                #pragma unroll
                for (int mi = 0; mi < 2; ++mi) {
                    const uint32_t off =
                        sw128((uint32_t)((wm * 32 + mi * 16 + arow) * 128 + kk * 32 + acol));
                    ldm_x4(ah[mi], uAh + off);
                    ldm_x4(al[mi], uAl + off);
                }
                uint32_t bh[4], bl[4];
                {
                    const uint32_t off =
                        sw128((uint32_t)((wn * 16 + brow) * 128 + kk * 32 + bcol));
                    ldm_x4(bh, uBh + off);
                    ldm_x4(bl, uBl + off);
                }
                #pragma unroll
                for (int mi = 0; mi < 2; ++mi)
                    #pragma unroll
                    for (int j = 0; j < 2; ++j) {
                        float* cc = c[mi][j];
                        mma_bf16(cc, ah[mi], &bh[j * 2]);
                        mma_bf16(cc, ah[mi], &bl[j * 2]);
                        mma_bf16(cc, al[mi], &bh[j * 2]);
                    }
            }
            if (pf) {
                store_split(rA, nb, nb + 8192, tid);
                store_split(rB, nb + 16384, nb + 24576, tid);
            }
        }

        // epilogue: GELU + store
        const int r0 = lane >> 2, cp = (lane & 3) * 2;
        #pragma unroll
        for (int mi = 0; mi < 2; ++mi)
            #pragma unroll
            for (int nj = 0; nj < 2; ++nj) {
                const int rloc = wm * 32 + mi * 16 + r0;
                const int ncol = f0 + wn * 16 + nj * 8 + cp;
                if (rloc < va) {
                    float2 o = make_float2(gelu_exact(c[mi][nj][0]), gelu_exact(c[mi][nj][1]));
                    *(float2*)&g_h[(size_t)(base + mm + rloc) * NF + ncol] = o;
                }
                if (rloc + 8 < va) {
                    float2 o = make_float2(gelu_exact(c[mi][nj][2]), gelu_exact(c[mi][nj][3]));
                    *(float2*)&g_h[(size_t)(base + mm + rloc + 8) * NF + ncol] = o;
                }
            }
        __syncthreads();
    }
}

// ---------------- zero out ----------------
__global__ void zero_out(float4* __restrict__ out) {
    out[blockIdx.x * 256 + threadIdx.x] = make_float4(0.f, 0.f, 0.f, 0.f);
}

// ---------------- GEMM2: out += h @ w2[e]  (k-split x2, atomic epilogue) -----
// CTA: (n-slab 64, expert, k-half). M=64 padded, K-tiles of 64 (16 per half).
__global__ void __launch_bounds__(256, 2) gemm2_tc(const float* __restrict__ w2,
                                                   float* __restrict__ out,
                                                   const int* __restrict__ counts) {
    extern __shared__ char sm[];
    const int e  = blockIdx.y;
    const int n0 = blockIdx.x * 64;
    const int kb = blockIdx.z * 1024;
    int base, cnt;
    expert_range(counts, e, base, cnt);
    const int tid = threadIdx.x, warp = tid >> 5, lane = tid & 31;
    const int wm = warp >> 2, wn = warp & 3;
    const float* w2e = w2 + (size_t)e * NF * NH + n0;

    const int arow = lane & 15, acol = lane & 16;   // A (plain)
    const int tbrow = lane & 15, tbcol = lane & 16; // B (trans, [k][n])

    for (int mm = 0; mm < cnt; mm += 64) {
        const int rem = cnt - mm;
        const int va = rem < 64 ? rem : 64;
        const float* ha = g_h + (size_t)(base + mm) * NF + kb;

        float c[2][2][4];
        #pragma unroll
        for (int i = 0; i < 2; ++i)
            #pragma unroll
            for (int j = 0; j < 2; ++j)
                #pragma unroll
                for (int q = 0; q < 4; ++q) c[i][j][q] = 0.f;

        {
            float4 rA[4], rB[4];
            load_f32(rA, ha, NF, va, tid);
            load_f32(rB, w2e + (size_t)kb * NH, NH, 64, tid);
            store_split(rA, sm, sm + 8192, tid);
            store_split(rB, sm + 16384, sm + 24576, tid);
        }

        for (int kt = 0; kt < 16; ++kt) {
            __syncthreads();
            char* bb = sm + (kt & 1) * BSZ;
            char* nb = sm + ((kt + 1) & 1) * BSZ;
            const bool pf = (kt + 1) < 16;
            float4 rA[4], rB[4];
            if (pf) {
                const int k0 = (kt + 1) * 64;
                load_f32(rA, ha + k0, NF, va, tid);
                load_f32(rB, w2e + (size_t)(kb + k0) * NH, NH, 64, tid);
            }
            const uint32_t uAh = smem_u32(bb), uAl = uAh + 8192;
            const uint32_t uBh = uAh + 16384, uBl = uAh + 24576;
            #pragma unroll
            for (int kk = 0; kk < 4; ++kk) {
                uint32_t ah[2][4], al[2][4];
                #pragma unroll
                for (int mi = 0; mi < 2; ++mi) {
                    const uint32_t off =
                        sw128((uint32_t)((wm * 32 + mi * 16 + arow) * 128 + kk * 32 + acol));
                    ldm_x4(ah[mi], uAh + off);
                    ldm_x4(al[mi], uAl + off);
                }
                uint32_t bh[4], bl[4];
                {
                    const uint32_t off =
                        sw128((uint32_t)((kk * 16 + tbrow) * 128 + wn * 32 + tbcol));
                    ldm_x4_t(bh, uBh + off);
                    ldm_x4_t(bl, uBl + off);
                }
                #pragma unroll
                for (int mi = 0; mi < 2; ++mi)
                    #pragma unroll
                    for (int j = 0; j < 2; ++j) {
                        float* cc = c[mi][j];
                        mma_bf16(cc, ah[mi], &bh[j * 2]);
                        mma_bf16(cc, ah[mi], &bl[j * 2]);
                        mma_bf16(cc, al[mi], &bh[j * 2]);
                    }
            }
            if (pf) {
                store_split(rA, nb, nb + 8192, tid);
                store_split(rB, nb + 16384, nb + 24576, tid);
            }
        }

        // epilogue: atomic accumulate (exactly 2 contributions per element)
        const int r0 = lane >> 2, cp = (lane & 3) * 2;
        #pragma unroll
        for (int mi = 0; mi < 2; ++mi)
            #pragma unroll
            for (int nj = 0; nj < 2; ++nj) {
                const int rloc = wm * 32 + mi * 16 + r0;
                const int ncol = n0 + wn * 16 + nj * 8 + cp;
                if (rloc < va) {
                    float* p = &out[(size_t)(base + mm + rloc) * NH + ncol];
                    atomicAdd(p, c[mi][nj][0]);
                    atomicAdd(p + 1, c[mi][nj][1]);
                }
                if (rloc + 8 < va) {
                    float* p = &out[(size_t)(base + mm + rloc + 8) * NH + ncol];
                    atomicAdd(p, c[mi][nj][2]);
                    atomicAdd(p + 1, c[mi][nj][3]);
                }
            }
        __syncthreads();
    }
}

// ---------------------------------------------------------------------------
extern "C" void kernel_launch(void* const* d_in, const int* in_sizes, int n_in,
                              void* d_out, int out_size) {
    const float* x  = (const float*)d_in[0];
    const float* w1 = (const float*)d_in[1];
    const float* w2 = (const float*)d_in[2];
    const int* tokens_per_expert = (const int*)d_in[3];
    float* out = (float*)d_out;

    cudaFuncSetAttribute(gemm1_tc, cudaFuncAttributeMaxDynamicSharedMemorySize, 2 * BSZ);
    cudaFuncSetAttribute(gemm2_tc, cudaFuncAttributeMaxDynamicSharedMemorySize, 2 * BSZ);

    gemm1_tc<<<dim3(NF / 64, NE), 256, 2 * BSZ>>>(x, w1, tokens_per_expert);
    zero_out<<<(NT * NH) / 1024, 256>>>((float4*)out);
    gemm2_tc<<<dim3(NH / 64, NE, 2), 256, 2 * BSZ>>>(w2, out, tokens_per_expert);
}